// round 13
// baseline (speedup 1.0000x reference)
#include <cuda_runtime.h>
#include <cuda_fp16.h>
#include <cstdint>

// ---------------- problem constants ----------------
static constexpr int M_TOTAL = 2048;     // queries
static constexpr int N_TOTAL = 65536;    // train points
static constexpr int D_      = 384;      // feature dim
static constexpr int BM = 128;           // CTA M tile
static constexpr int BN = 128;           // per n-tile; each CTA does 2 n-tiles
static constexpr int BK = 32;            // K per smem stage
static constexpr int KI = D_ / BK;       // 12
static constexpr int MT = M_TOTAL / BM;  // 16
static constexpr int NT2 = N_TOTAL / (2 * BN); // 256 CTA columns (2 tiles each)
static constexpr int NSTAGE = 4;

// smem: 4 stages x (A 8KB | B 8KB) + tt(1KB) + epi(4KB)
static constexpr int STG     = 16384;
static constexpr int SM_TT   = NSTAGE * STG;     // 65536
static constexpr int SM_EPI  = SM_TT + 1024;     // 66560
static constexpr int SMEM_TOTAL = SM_EPI + 128 * 4 * 8; // 70656

// ---------------- device scratch (no allocs allowed) ----------------
__device__ __half g_Xh[(long)N_TOTAL * D_];
__device__ __half g_xh[(long)M_TOTAL * D_];
__device__ float  g_tt[N_TOTAL];
__device__ unsigned long long g_part[(long)M_TOTAL * NT2 * 2];

// ---------------- helpers ----------------
__device__ __forceinline__ uint32_t smem_u32(const void* p) {
    uint32_t a;
    asm("{ .reg .u64 t; cvta.to.shared.u64 t, %1; cvt.u32.u64 %0, t; }" : "=r"(a) : "l"(p));
    return a;
}
__device__ __forceinline__ unsigned long long pack_key(float s, unsigned idx) {
    unsigned u = __float_as_uint(s);
    u = (u & 0x80000000u) ? ~u : (u | 0x80000000u);
    return ((unsigned long long)u << 32) | idx;
}
#define CP_ASYNC16(dst, src) \
    asm volatile("cp.async.cg.shared.global [%0], [%1], 16;" :: "r"(dst), "l"(src) : "memory")
#define CP_COMMIT()  asm volatile("cp.async.commit_group;" ::: "memory")
#define CP_WAIT2()   asm volatile("cp.async.wait_group 2;" ::: "memory")
#define CP_WAIT1()   asm volatile("cp.async.wait_group 1;" ::: "memory")
#define CP_WAIT0()   asm volatile("cp.async.wait_group 0;" ::: "memory")

#define LDMX4(r, addr) \
    asm volatile("ldmatrix.sync.aligned.m8n8.x4.shared.b16 {%0,%1,%2,%3}, [%4];" \
        : "=r"((r)[0]), "=r"((r)[1]), "=r"((r)[2]), "=r"((r)[3]) : "r"(addr))

#define MMA16816(d, a, b0, b1) \
    asm volatile("mma.sync.aligned.m16n8k16.row.col.f32.f16.f16.f32 " \
        "{%0,%1,%2,%3}, {%4,%5,%6,%7}, {%8,%9}, {%0,%1,%2,%3};" \
        : "+f"((d)[0]), "+f"((d)[1]), "+f"((d)[2]), "+f"((d)[3]) \
        : "r"((a)[0]), "r"((a)[1]), "r"((a)[2]), "r"((a)[3]), "r"(b0), "r"(b1))

// merge two ascending pairs (b1<=b2), (o1<=o2) -> global top-2 in (b1,b2)
__device__ __forceinline__ void merge2(unsigned long long& b1, unsigned long long& b2,
                                       unsigned long long o1, unsigned long long o2) {
    if (o1 < b1) { b2 = (b1 < o2) ? b1 : o2; b1 = o1; }
    else         { b2 = (b2 < o1) ? b2 : o1; }
}

// ================= kernel 1: fp16 convert + tt =================
__global__ void knn_prep(const float* __restrict__ Xt, const float* __restrict__ x) {
    int gw  = (blockIdx.x * blockDim.x + threadIdx.x) >> 5;
    int lid = threadIdx.x & 31;
    if (gw >= N_TOTAL + M_TOTAL) return;
    bool isX = gw < N_TOTAL;
    long row = isX ? gw : (gw - N_TOTAL);
    const float* src = (isX ? Xt : x) + row * D_;
    __half* dst = (isX ? g_Xh : g_xh) + row * D_;

    float ss = 0.f;
    #pragma unroll
    for (int i = lid; i < D_ / 4; i += 32) {
        float4 v = reinterpret_cast<const float4*>(src)[i];
        ss += v.x * v.x + v.y * v.y + v.z * v.z + v.w * v.w;
        __half2* hp = reinterpret_cast<__half2*>(dst + i * 4);
        hp[0] = __floats2half2_rn(v.x, v.y);
        hp[1] = __floats2half2_rn(v.z, v.w);
    }
    #pragma unroll
    for (int o = 16; o; o >>= 1) ss += __shfl_xor_sync(0xffffffffu, ss, o);
    if (lid == 0 && isX) g_tt[row] = ss;
}

// ================= kernel 2: fp16 mma.sync GEMM, 2 n-tiles per CTA =================
__device__ __forceinline__ void issue_stage(uint32_t sb, int kk, int m0, int nbase, int tid) {
    uint32_t stb = sb + (uint32_t)(kk & (NSTAGE - 1)) * STG;
    int kbase = kk * BK;
    #pragma unroll
    for (int j = 0; j < 4; j++) {
        int i = tid + j * 256;
        int r = (i >> 2) & 127, c = i & 3;
        uint32_t swc = (uint32_t)(c ^ ((r >> 1) & 3));
        const __half* src;
        uint32_t dst;
        if (i < 512) { // A
            src = g_xh + (long)(m0 + r) * D_ + kbase + c * 8;
            dst = stb + (uint32_t)(r * 64) + swc * 16;
        } else {       // B
            src = g_Xh + (long)(nbase + r) * D_ + kbase + c * 8;
            dst = stb + 8192u + (uint32_t)(r * 64) + swc * 16;
        }
        CP_ASYNC16(dst, src);
    }
    CP_COMMIT();
}

__global__ void __launch_bounds__(256, 2) knn_gemm() {
    extern __shared__ __align__(128) char smem[];
    uint32_t sb = smem_u32(smem);
    int tid = threadIdx.x, wid = tid >> 5, lid = tid & 31;
    int wm = wid >> 1, wn = wid & 1;          // 4x2 warp grid, 32x64 warp tile
    int m0 = blockIdx.x * BM;
    int n0 = blockIdx.y * (2 * BN);           // this CTA covers [n0, n0+256)

    // tt for both tiles (256 floats)
    reinterpret_cast<float*>(smem + SM_TT)[tid] = g_tt[n0 + tid];

    float acc[2][8][4];

    const int a_r_lane = lid & 15;            // row within 16
    const int a_chi    = lid >> 4;            // chunk low bit
    const int b_n_lane = ((lid >> 4) & 1) * 8 + (lid & 7);
    const int b_chi    = (lid >> 3) & 1;

    // ---- frozen R7 k-loop over one 128-col n-tile ----
    auto kloop = [&](int nbase) {
        for (int kk = 0; kk < KI; ++kk) {
            if (kk < KI - 2)      { CP_WAIT2(); }
            else if (kk == KI - 2){ CP_WAIT1(); }
            else                  { CP_WAIT0(); }
            __syncthreads();
            if (kk + 3 < KI) issue_stage(sb, kk + 3, m0, nbase, tid);

            uint32_t Ab = sb + (uint32_t)(kk & (NSTAGE - 1)) * STG;
            uint32_t Bb = Ab + 8192u;

            uint32_t a_frag[2][2][4];
            #pragma unroll
            for (int ks = 0; ks < 2; ++ks) {
                #pragma unroll
                for (int mf = 0; mf < 2; ++mf) {
                    int r = wm * 32 + mf * 16 + a_r_lane;
                    uint32_t craw = (uint32_t)(2 * ks + a_chi);
                    uint32_t addr = Ab + (uint32_t)(r * 64) + ((craw ^ ((uint32_t)(r >> 1) & 3u)) * 16u);
                    LDMX4(a_frag[ks][mf], addr);
                }
            }
            #pragma unroll
            for (int ks = 0; ks < 2; ++ks) {
                uint32_t b4[2][4];
                {
                    int n = wn * 64 + b_n_lane;
                    uint32_t craw = (uint32_t)(2 * ks + b_chi);
                    uint32_t addr = Bb + (uint32_t)(n * 64) + ((craw ^ ((uint32_t)(n >> 1) & 3u)) * 16u);
                    LDMX4(b4[0], addr);
                }
                #pragma unroll
                for (int np = 0; np < 4; ++np) {
                    if (np < 3) {
                        int n = wn * 64 + (np + 1) * 16 + b_n_lane;
                        uint32_t craw = (uint32_t)(2 * ks + b_chi);
                        uint32_t addr = Bb + (uint32_t)(n * 64) + ((craw ^ ((uint32_t)(n >> 1) & 3u)) * 16u);
                        LDMX4(b4[(np + 1) & 1], addr);
                    }
                    uint32_t* bc = b4[np & 1];
                    MMA16816(acc[0][2 * np],     a_frag[ks][0], bc[0], bc[1]);
                    MMA16816(acc[0][2 * np + 1], a_frag[ks][0], bc[2], bc[3]);
                    MMA16816(acc[1][2 * np],     a_frag[ks][1], bc[0], bc[1]);
                    MMA16816(acc[1][2 * np + 1], a_frag[ks][1], bc[2], bc[3]);
                }
            }
        }
    };

    // ---- epilogue for one tile: per-row top-2 into epi, then tid<128 merge ----
    const float* tts = reinterpret_cast<const float*>(smem + SM_TT);
    unsigned long long* epi = reinterpret_cast<unsigned long long*>(smem + SM_EPI);

    auto epilogue = [&](int tile, unsigned long long& rb1, unsigned long long& rb2) {
        #pragma unroll
        for (int mf = 0; mf < 2; ++mf) {
            #pragma unroll
            for (int h = 0; h < 2; ++h) {
                int R = wm * 32 + mf * 16 + (lid >> 2) + 8 * h;
                unsigned long long b1 = ~0ull, b2 = ~0ull;
                #pragma unroll
                for (int nf = 0; nf < 8; ++nf) {
                    #pragma unroll
                    for (int j = 0; j < 2; ++j) {
                        int col = wn * 64 + nf * 8 + (lid & 3) * 2 + j;
                        float score = tts[tile * 128 + col] - 2.0f * acc[mf][nf][2 * h + j];
                        unsigned long long key = pack_key(score, (unsigned)(n0 + tile * 128 + col));
                        if (key < b1) { b2 = b1; b1 = key; }
                        else if (key < b2) { b2 = key; }
                    }
                }
                unsigned long long o1 = __shfl_xor_sync(0xffffffffu, b1, 1);
                unsigned long long o2 = __shfl_xor_sync(0xffffffffu, b2, 1);
                merge2(b1, b2, o1, o2);
                o1 = __shfl_xor_sync(0xffffffffu, b1, 2);
                o2 = __shfl_xor_sync(0xffffffffu, b2, 2);
                merge2(b1, b2, o1, o2);
                if ((lid & 3) == 0) {
                    epi[R * 4 + wn * 2 + 0] = b1;
                    epi[R * 4 + wn * 2 + 1] = b2;
                }
            }
        }
        __syncthreads();
        if (tid < BM) {
            unsigned long long b1 = epi[tid * 4 + 0], b2 = epi[tid * 4 + 1];
            merge2(b1, b2, epi[tid * 4 + 2], epi[tid * 4 + 3]);
            merge2(rb1, rb2, b1, b2);
        }
    };

    // ================== tile 0 ==================
    #pragma unroll
    for (int mf = 0; mf < 2; mf++)
        #pragma unroll
        for (int nf = 0; nf < 8; nf++)
            #pragma unroll
            for (int k = 0; k < 4; k++) acc[mf][nf][k] = 0.f;

    issue_stage(sb, 0, m0, n0, tid);
    issue_stage(sb, 1, m0, n0, tid);
    issue_stage(sb, 2, m0, n0, tid);

    kloop(n0);

    // all warps done reading tile-0 buffers -> safe to refill for tile 1
    __syncthreads();
    issue_stage(sb, 0, m0, n0 + BN, tid);
    issue_stage(sb, 1, m0, n0 + BN, tid);
    issue_stage(sb, 2, m0, n0 + BN, tid);

    unsigned long long rb1 = ~0ull, rb2 = ~0ull;   // running per-row top-2 (tid<128)
    epilogue(0, rb1, rb2);        // overlaps with tile-1 prologue copies in flight

    // reset accumulators for tile 1
    #pragma unroll
    for (int mf = 0; mf < 2; mf++)
        #pragma unroll
        for (int nf = 0; nf < 8; nf++)
            #pragma unroll
            for (int k = 0; k < 4; k++) acc[mf][nf][k] = 0.f;

    // ================== tile 1 ==================
    kloop(n0 + BN);               // first wait completes tile-1 stage 0 (already landed)
    epilogue(1, rb1, rb2);

    if (tid < BM) {
        long base = ((long)(m0 + tid) * NT2 + blockIdx.y) * 2;
        g_part[base] = rb1;
        g_part[base + 1] = rb2;
    }
}

// ================= kernel 3: shuffle-only global top-4 + exact rescore + gather =================
__global__ void knn_reduce(const float* __restrict__ x, const float* __restrict__ Xt,
                           const float* __restrict__ Yt, float* __restrict__ out) {
    int row = blockIdx.x, tid = threadIdx.x;
    int wid = tid >> 5, lid = tid & 31;
    const unsigned long long* part = g_part + (long)row * NT2 * 2;

    // 512 keys/row, 2 per thread (ordered pair)
    unsigned long long b1 = part[tid * 2], b2 = part[tid * 2 + 1];
    // warp shuffle-merge -> warp top-2
    #pragma unroll
    for (int o = 16; o; o >>= 1) {
        unsigned long long o1 = __shfl_xor_sync(0xffffffffu, b1, o);
        unsigned long long o2 = __shfl_xor_sync(0xffffffffu, b2, o);
        merge2(b1, b2, o1, o2);
    }
    __shared__ unsigned long long w2[16];
    if (lid == 0) { w2[wid * 2] = b1; w2[wid * 2 + 1] = b2; }
    __syncthreads();

    // warp 0: extract global top-4 of the 16 candidates (keys distinct by idx)
    __shared__ unsigned cand[4];
    if (wid == 0) {
        unsigned long long k = (lid < 16) ? w2[lid] : ~0ull;
        #pragma unroll
        for (int r = 0; r < 4; r++) {
            unsigned long long m = k;
            #pragma unroll
            for (int o = 16; o; o >>= 1) {
                unsigned long long om = __shfl_xor_sync(0xffffffffu, m, o);
                if (om < m) m = om;
            }
            if (lid == 0) cand[r] = (unsigned)(m & 0xffffffffu);
            if (k == m) k = ~0ull;
        }
    }
    __syncthreads();

    // exact fp32 rescore of 4 candidates (one per warp, warps 0-3)
    __shared__ float sscore[4];
    __shared__ unsigned sidx[4];
    if (wid < 4) {
        unsigned idx = cand[wid];
        const float* xr = x + (long)row * D_;
        const float* tr = Xt + (long)idx * D_;
        float p = 0.f;
        #pragma unroll
        for (int e = lid; e < D_; e += 32) p += xr[e] * tr[e];
        #pragma unroll
        for (int o = 16; o; o >>= 1) p += __shfl_xor_sync(0xffffffffu, p, o);
        if (lid == 0) { sscore[wid] = g_tt[idx] - 2.0f * p; sidx[wid] = idx; }
    }
    __syncthreads();
    __shared__ unsigned winner;
    if (tid == 0) {
        float bs = sscore[0]; unsigned bi = sidx[0];
        #pragma unroll
        for (int i = 1; i < 4; i++)
            if (sscore[i] < bs || (sscore[i] == bs && sidx[i] < bi)) { bs = sscore[i]; bi = sidx[i]; }
        winner = bi;
    }
    __syncthreads();
    if (tid < 24) out[row * 24 + tid] = Yt[(long)winner * 24 + tid];
}

// ================= launch =================
extern "C" void kernel_launch(void* const* d_in, const int* in_sizes, int n_in,
                              void* d_out, int out_size) {
    const float* x  = (const float*)d_in[0];   // [2048, 24, 16]
    const float* Xt = (const float*)d_in[1];   // [65536, 384]
    const float* Yt = (const float*)d_in[2];   // [65536, 24, 1]
    float* out = (float*)d_out;                // [2048, 24, 1]

    cudaFuncSetAttribute(knn_gemm, cudaFuncAttributeMaxDynamicSharedMemorySize, SMEM_TOTAL);

    int total_warps = N_TOTAL + M_TOTAL;               // 67584
    knn_prep<<<total_warps / 8, 256>>>(Xt, x);
    knn_gemm<<<dim3(MT, NT2), 256, SMEM_TOTAL>>>();
    knn_reduce<<<M_TOTAL, 256>>>(x, Xt, Yt, out);
}

// round 14
// speedup vs baseline: 1.0773x; 1.0773x over previous
#include <cuda_runtime.h>
#include <cuda_fp16.h>
#include <cstdint>

// ---------------- problem constants ----------------
static constexpr int M_TOTAL = 2048;     // queries
static constexpr int N_TOTAL = 65536;    // train points
static constexpr int D_      = 384;      // feature dim
static constexpr int BM = 128;           // CTA M tile
static constexpr int BN = 128;           // CTA N tile
static constexpr int BK = 64;            // K per smem stage (4 x k16 halves)
static constexpr int KI = D_ / BK;       // 6
static constexpr int MT = M_TOTAL / BM;  // 16
static constexpr int NT = N_TOTAL / BN;  // 512
static constexpr int NSTAGE = 3;

// smem: 3 stages x (A 16KB | B 16KB) + tt(512B) + epi(4KB)
static constexpr int STG     = 32768;
static constexpr int SM_TT   = NSTAGE * STG;     // 98304
static constexpr int SM_EPI  = SM_TT + 512;      // 98816
static constexpr int SMEM_TOTAL = SM_EPI + 128 * 4 * 8; // 102912 (x2 CTAs = 206KB)

// ---------------- device scratch (no allocs allowed) ----------------
__device__ __half g_Xh[(long)N_TOTAL * D_];
__device__ __half g_xh[(long)M_TOTAL * D_];
__device__ float  g_tt[N_TOTAL];
__device__ unsigned long long g_part[(long)M_TOTAL * NT * 2];

// ---------------- helpers ----------------
__device__ __forceinline__ uint32_t smem_u32(const void* p) {
    uint32_t a;
    asm("{ .reg .u64 t; cvta.to.shared.u64 t, %1; cvt.u32.u64 %0, t; }" : "=r"(a) : "l"(p));
    return a;
}
__device__ __forceinline__ unsigned long long pack_key(float s, unsigned idx) {
    unsigned u = __float_as_uint(s);
    u = (u & 0x80000000u) ? ~u : (u | 0x80000000u);
    return ((unsigned long long)u << 32) | idx;
}
#define CP_ASYNC16(dst, src) \
    asm volatile("cp.async.cg.shared.global [%0], [%1], 16;" :: "r"(dst), "l"(src) : "memory")
#define CP_COMMIT()  asm volatile("cp.async.commit_group;" ::: "memory")
#define CP_WAIT1()   asm volatile("cp.async.wait_group 1;" ::: "memory")
#define CP_WAIT0()   asm volatile("cp.async.wait_group 0;" ::: "memory")

#define LDMX4(r, addr) \
    asm volatile("ldmatrix.sync.aligned.m8n8.x4.shared.b16 {%0,%1,%2,%3}, [%4];" \
        : "=r"((r)[0]), "=r"((r)[1]), "=r"((r)[2]), "=r"((r)[3]) : "r"(addr))

#define MMA16816(d, a, b0, b1) \
    asm volatile("mma.sync.aligned.m16n8k16.row.col.f32.f16.f16.f32 " \
        "{%0,%1,%2,%3}, {%4,%5,%6,%7}, {%8,%9}, {%0,%1,%2,%3};" \
        : "+f"((d)[0]), "+f"((d)[1]), "+f"((d)[2]), "+f"((d)[3]) \
        : "r"((a)[0]), "r"((a)[1]), "r"((a)[2]), "r"((a)[3]), "r"(b0), "r"(b1))

// merge two ascending pairs (b1<=b2), (o1<=o2) -> global top-2 in (b1,b2)
__device__ __forceinline__ void merge2(unsigned long long& b1, unsigned long long& b2,
                                       unsigned long long o1, unsigned long long o2) {
    if (o1 < b1) { b2 = (b1 < o2) ? b1 : o2; b1 = o1; }
    else         { b2 = (b2 < o1) ? b2 : o1; }
}

// ================= kernel 1: fp16 convert + tt =================
__global__ void knn_prep(const float* __restrict__ Xt, const float* __restrict__ x) {
    int gw  = (blockIdx.x * blockDim.x + threadIdx.x) >> 5;
    int lid = threadIdx.x & 31;
    if (gw >= N_TOTAL + M_TOTAL) return;
    bool isX = gw < N_TOTAL;
    long row = isX ? gw : (gw - N_TOTAL);
    const float* src = (isX ? Xt : x) + row * D_;
    __half* dst = (isX ? g_Xh : g_xh) + row * D_;

    float ss = 0.f;
    #pragma unroll
    for (int i = lid; i < D_ / 4; i += 32) {
        float4 v = reinterpret_cast<const float4*>(src)[i];
        ss += v.x * v.x + v.y * v.y + v.z * v.z + v.w * v.w;
        __half2* hp = reinterpret_cast<__half2*>(dst + i * 4);
        hp[0] = __floats2half2_rn(v.x, v.y);
        hp[1] = __floats2half2_rn(v.z, v.w);
    }
    #pragma unroll
    for (int o = 16; o; o >>= 1) ss += __shfl_xor_sync(0xffffffffu, ss, o);
    if (lid == 0 && isX) g_tt[row] = ss;
}

// ================= kernel 2: fp16 mma.sync GEMM, BK=64 (6 iters, 6 barriers) =================
// smem rows are 128B (8 x 16B chunks); swizzle: phys_chunk = c ^ (r & 7).
__device__ __forceinline__ void issue_stage(uint32_t sb, int kk, int m0, int n0, int tid) {
    uint32_t stb = sb + (uint32_t)(kk % NSTAGE) * STG;
    int kbase = kk * BK;
    #pragma unroll
    for (int j = 0; j < 8; j++) {
        int i = tid + j * 256;
        int r = (i >> 3) & 127, c = i & 7;
        uint32_t swc = (uint32_t)(c ^ (r & 7));
        const __half* src;
        uint32_t dst;
        if (i < 1024) { // A: 128 rows x 8 chunks
            src = g_xh + (long)(m0 + r) * D_ + kbase + c * 8;
            dst = stb + (uint32_t)(r * 128) + swc * 16;
        } else {        // B: 128 rows x 8 chunks
            src = g_Xh + (long)(n0 + r) * D_ + kbase + c * 8;
            dst = stb + 16384u + (uint32_t)(r * 128) + swc * 16;
        }
        CP_ASYNC16(dst, src);
    }
    CP_COMMIT();
}

__global__ void __launch_bounds__(256, 2) knn_gemm() {
    extern __shared__ __align__(128) char smem[];
    uint32_t sb = smem_u32(smem);
    int tid = threadIdx.x, wid = tid >> 5, lid = tid & 31;
    int wm = wid >> 1, wn = wid & 1;          // 4x2 warp grid, 32x64 warp tile
    int m0 = blockIdx.x * BM;
    int n0 = blockIdx.y * BN;

    // tt tile
    if (tid < BN) reinterpret_cast<float*>(smem + SM_TT)[tid] = g_tt[n0 + tid];

    float acc[2][8][4];
    #pragma unroll
    for (int mf = 0; mf < 2; mf++)
        #pragma unroll
        for (int nf = 0; nf < 8; nf++)
            #pragma unroll
            for (int k = 0; k < 4; k++) acc[mf][nf][k] = 0.f;

    issue_stage(sb, 0, m0, n0, tid);
    issue_stage(sb, 1, m0, n0, tid);

    const int a_r_lane = lid & 15;            // row within 16
    const int a_chi    = lid >> 4;            // 16B chunk low bit within k16 pair
    const int b_n_lane = ((lid >> 4) & 1) * 8 + (lid & 7);
    const int b_chi    = (lid >> 3) & 1;

    for (int kk = 0; kk < KI; ++kk) {
        if (kk < KI - 1) { CP_WAIT1(); } else { CP_WAIT0(); }
        __syncthreads();
        // refill buffer (kk+2)%3 == (kk-1)%3: last read in iter kk-1,
        // proven complete by the barrier above.
        if (kk + 2 < KI) issue_stage(sb, kk + 2, m0, n0, tid);

        uint32_t Ab = sb + (uint32_t)(kk % NSTAGE) * STG;
        uint32_t Bb = Ab + 16384u;

        #pragma unroll
        for (int ks = 0; ks < 4; ++ks) {      // four k16 halves per 64-deep stage
            // A fragments for this half (loaded per-half: low register pressure)
            uint32_t a_frag[2][4];
            #pragma unroll
            for (int mf = 0; mf < 2; ++mf) {
                int r = wm * 32 + mf * 16 + a_r_lane;
                uint32_t craw = (uint32_t)(2 * ks + a_chi);
                uint32_t addr = Ab + (uint32_t)(r * 128) + ((craw ^ ((uint32_t)r & 7u)) * 16u);
                LDMX4(a_frag[mf], addr);
            }
            uint32_t b4[2][4];
            {
                int n = wn * 64 + b_n_lane;
                uint32_t craw = (uint32_t)(2 * ks + b_chi);
                uint32_t addr = Bb + (uint32_t)(n * 128) + ((craw ^ ((uint32_t)n & 7u)) * 16u);
                LDMX4(b4[0], addr);
            }
            #pragma unroll
            for (int np = 0; np < 4; ++np) {
                if (np < 3) {   // prefetch next B fragment before issuing MMAs
                    int n = wn * 64 + (np + 1) * 16 + b_n_lane;
                    uint32_t craw = (uint32_t)(2 * ks + b_chi);
                    uint32_t addr = Bb + (uint32_t)(n * 128) + ((craw ^ ((uint32_t)n & 7u)) * 16u);
                    LDMX4(b4[(np + 1) & 1], addr);
                }
                uint32_t* bc = b4[np & 1];
                MMA16816(acc[0][2 * np],     a_frag[0], bc[0], bc[1]);
                MMA16816(acc[0][2 * np + 1], a_frag[0], bc[2], bc[3]);
                MMA16816(acc[1][2 * np],     a_frag[1], bc[0], bc[1]);
                MMA16816(acc[1][2 * np + 1], a_frag[1], bc[2], bc[3]);
            }
        }
    }

    // ---- epilogue: score = tt - 2*cross; per-row top-2 over this 128-col tile ----
    const float* tts = reinterpret_cast<const float*>(smem + SM_TT);
    unsigned long long* epi = reinterpret_cast<unsigned long long*>(smem + SM_EPI);

    #pragma unroll
    for (int mf = 0; mf < 2; ++mf) {
        #pragma unroll
        for (int h = 0; h < 2; ++h) {
            int R = wm * 32 + mf * 16 + (lid >> 2) + 8 * h;
            unsigned long long b1 = ~0ull, b2 = ~0ull;
            #pragma unroll
            for (int nf = 0; nf < 8; ++nf) {
                #pragma unroll
                for (int j = 0; j < 2; ++j) {
                    int col = wn * 64 + nf * 8 + (lid & 3) * 2 + j;
                    float score = tts[col] - 2.0f * acc[mf][nf][2 * h + j];
                    unsigned long long key = pack_key(score, (unsigned)(n0 + col));
                    if (key < b1) { b2 = b1; b1 = key; }
                    else if (key < b2) { b2 = key; }
                }
            }
            unsigned long long o1 = __shfl_xor_sync(0xffffffffu, b1, 1);
            unsigned long long o2 = __shfl_xor_sync(0xffffffffu, b2, 1);
            merge2(b1, b2, o1, o2);
            o1 = __shfl_xor_sync(0xffffffffu, b1, 2);
            o2 = __shfl_xor_sync(0xffffffffu, b2, 2);
            merge2(b1, b2, o1, o2);
            if ((lid & 3) == 0) {
                epi[R * 4 + wn * 2 + 0] = b1;
                epi[R * 4 + wn * 2 + 1] = b2;
            }
        }
    }
    __syncthreads();
    if (tid < BM) {
        unsigned long long b1 = epi[tid * 4 + 0], b2 = epi[tid * 4 + 1];
        merge2(b1, b2, epi[tid * 4 + 2], epi[tid * 4 + 3]);
        long base = ((long)(m0 + tid) * NT + blockIdx.y) * 2;
        g_part[base] = b1;
        g_part[base + 1] = b2;
    }
}

// ================= kernel 3: shuffle-only global top-4 + exact rescore + gather =================
__global__ void knn_reduce(const float* __restrict__ x, const float* __restrict__ Xt,
                           const float* __restrict__ Yt, float* __restrict__ out) {
    int row = blockIdx.x, tid = threadIdx.x;
    int wid = tid >> 5, lid = tid & 31;
    const unsigned long long* part = g_part + (long)row * NT * 2;

    // per-thread top-2 of its 4 keys
    unsigned long long b1 = ~0ull, b2 = ~0ull;
    #pragma unroll
    for (int j = 0; j < 4; j++) {
        unsigned long long k = part[tid * 4 + j];
        if (k < b1) { b2 = b1; b1 = k; }
        else if (k < b2) { b2 = k; }
    }
    // warp shuffle-merge -> warp top-2
    #pragma unroll
    for (int o = 16; o; o >>= 1) {
        unsigned long long o1 = __shfl_xor_sync(0xffffffffu, b1, o);
        unsigned long long o2 = __shfl_xor_sync(0xffffffffu, b2, o);
        merge2(b1, b2, o1, o2);
    }
    __shared__ unsigned long long w2[16];
    if (lid == 0) { w2[wid * 2] = b1; w2[wid * 2 + 1] = b2; }
    __syncthreads();

    // warp 0: extract global top-4 of the 16 candidates (keys distinct by idx)
    __shared__ unsigned cand[4];
    if (wid == 0) {
        unsigned long long k = (lid < 16) ? w2[lid] : ~0ull;
        #pragma unroll
        for (int r = 0; r < 4; r++) {
            unsigned long long m = k;
            #pragma unroll
            for (int o = 16; o; o >>= 1) {
                unsigned long long om = __shfl_xor_sync(0xffffffffu, m, o);
                if (om < m) m = om;
            }
            if (lid == 0) cand[r] = (unsigned)(m & 0xffffffffu);
            if (k == m) k = ~0ull;
        }
    }
    __syncthreads();

    // exact fp32 rescore of 4 candidates (one per warp, warps 0-3)
    __shared__ float sscore[4];
    __shared__ unsigned sidx[4];
    if (wid < 4) {
        unsigned idx = cand[wid];
        const float* xr = x + (long)row * D_;
        const float* tr = Xt + (long)idx * D_;
        float p = 0.f;
        #pragma unroll
        for (int e = lid; e < D_; e += 32) p += xr[e] * tr[e];
        #pragma unroll
        for (int o = 16; o; o >>= 1) p += __shfl_xor_sync(0xffffffffu, p, o);
        if (lid == 0) { sscore[wid] = g_tt[idx] - 2.0f * p; sidx[wid] = idx; }
    }
    __syncthreads();
    __shared__ unsigned winner;
    if (tid == 0) {
        float bs = sscore[0]; unsigned bi = sidx[0];
        #pragma unroll
        for (int i = 1; i < 4; i++)
            if (sscore[i] < bs || (sscore[i] == bs && sidx[i] < bi)) { bs = sscore[i]; bi = sidx[i]; }
        winner = bi;
    }
    __syncthreads();
    if (tid < 24) out[row * 24 + tid] = Yt[(long)winner * 24 + tid];
}

// ================= launch =================
extern "C" void kernel_launch(void* const* d_in, const int* in_sizes, int n_in,
                              void* d_out, int out_size) {
    const float* x  = (const float*)d_in[0];   // [2048, 24, 16]
    const float* Xt = (const float*)d_in[1];   // [65536, 384]
    const float* Yt = (const float*)d_in[2];   // [65536, 24, 1]
    float* out = (float*)d_out;                // [2048, 24, 1]

    cudaFuncSetAttribute(knn_gemm, cudaFuncAttributeMaxDynamicSharedMemorySize, SMEM_TOTAL);

    int total_warps = N_TOTAL + M_TOTAL;               // 67584
    knn_prep<<<total_warps / 8, 256>>>(Xt, x);
    knn_gemm<<<dim3(MT, NT), 256, SMEM_TOTAL>>>();
    knn_reduce<<<M_TOTAL, 256>>>(x, Xt, Yt, out);
}

// round 15
// speedup vs baseline: 1.2807x; 1.1888x over previous
#include <cuda_runtime.h>
#include <cuda_fp16.h>
#include <cstdint>

// ---------------- problem constants ----------------
static constexpr int M_TOTAL = 2048;     // queries
static constexpr int N_TOTAL = 65536;    // train points
static constexpr int D_      = 384;      // feature dim
static constexpr int BM = 128;           // CTA M tile
static constexpr int BN = 128;           // CTA N tile
static constexpr int BK = 32;            // K per smem stage
static constexpr int KI = D_ / BK;       // 12
static constexpr int MT = M_TOTAL / BM;  // 16
static constexpr int NT = N_TOTAL / BN;  // 512
static constexpr int NSTAGE = 4;

// smem: 4 stages x (A 8KB | B 8KB) + tt(512B) + epi(4KB)
static constexpr int STG     = 16384;
static constexpr int SM_TT   = NSTAGE * STG;     // 65536
static constexpr int SM_EPI  = SM_TT + 512;      // 66048
static constexpr int SMEM_TOTAL = SM_EPI + 128 * 4 * 8; // 70144

// ---------------- device scratch (no allocs allowed) ----------------
__device__ __half g_Xh[(long)N_TOTAL * D_];
__device__ __half g_xh[(long)M_TOTAL * D_];
__device__ float  g_tt[N_TOTAL];
__device__ unsigned long long g_part[(long)M_TOTAL * NT * 2];

// ---------------- helpers ----------------
__device__ __forceinline__ uint32_t smem_u32(const void* p) {
    uint32_t a;
    asm("{ .reg .u64 t; cvta.to.shared.u64 t, %1; cvt.u32.u64 %0, t; }" : "=r"(a) : "l"(p));
    return a;
}
__device__ __forceinline__ unsigned long long pack_key(float s, unsigned idx) {
    unsigned u = __float_as_uint(s);
    u = (u & 0x80000000u) ? ~u : (u | 0x80000000u);
    return ((unsigned long long)u << 32) | idx;
}
#define CP_ASYNC16(dst, src) \
    asm volatile("cp.async.cg.shared.global [%0], [%1], 16;" :: "r"(dst), "l"(src) : "memory")
#define CP_COMMIT()  asm volatile("cp.async.commit_group;" ::: "memory")
#define CP_WAIT2()   asm volatile("cp.async.wait_group 2;" ::: "memory")
#define CP_WAIT1()   asm volatile("cp.async.wait_group 1;" ::: "memory")
#define CP_WAIT0()   asm volatile("cp.async.wait_group 0;" ::: "memory")

#define LDMX4(r, addr) \
    asm volatile("ldmatrix.sync.aligned.m8n8.x4.shared.b16 {%0,%1,%2,%3}, [%4];" \
        : "=r"((r)[0]), "=r"((r)[1]), "=r"((r)[2]), "=r"((r)[3]) : "r"(addr))

#define MMA16816(d, a, b0, b1) \
    asm volatile("mma.sync.aligned.m16n8k16.row.col.f32.f16.f16.f32 " \
        "{%0,%1,%2,%3}, {%4,%5,%6,%7}, {%8,%9}, {%0,%1,%2,%3};" \
        : "+f"((d)[0]), "+f"((d)[1]), "+f"((d)[2]), "+f"((d)[3]) \
        : "r"((a)[0]), "r"((a)[1]), "r"((a)[2]), "r"((a)[3]), "r"(b0), "r"(b1))

// merge two ascending pairs (b1<=b2), (o1<=o2) -> global top-2 in (b1,b2)
__device__ __forceinline__ void merge2(unsigned long long& b1, unsigned long long& b2,
                                       unsigned long long o1, unsigned long long o2) {
    if (o1 < b1) { b2 = (b1 < o2) ? b1 : o2; b1 = o1; }
    else         { b2 = (b2 < o1) ? b2 : o1; }
}

// ================= kernel 1: fp16 convert + tt =================
__global__ void knn_prep(const float* __restrict__ Xt, const float* __restrict__ x) {
    int gw  = (blockIdx.x * blockDim.x + threadIdx.x) >> 5;
    int lid = threadIdx.x & 31;
    if (gw >= N_TOTAL + M_TOTAL) return;
    bool isX = gw < N_TOTAL;
    long row = isX ? gw : (gw - N_TOTAL);
    const float* src = (isX ? Xt : x) + row * D_;
    __half* dst = (isX ? g_Xh : g_xh) + row * D_;

    float ss = 0.f;
    #pragma unroll
    for (int i = lid; i < D_ / 4; i += 32) {
        float4 v = reinterpret_cast<const float4*>(src)[i];
        ss += v.x * v.x + v.y * v.y + v.z * v.z + v.w * v.w;
        __half2* hp = reinterpret_cast<__half2*>(dst + i * 4);
        hp[0] = __floats2half2_rn(v.x, v.y);
        hp[1] = __floats2half2_rn(v.z, v.w);
    }
    #pragma unroll
    for (int o = 16; o; o >>= 1) ss += __shfl_xor_sync(0xffffffffu, ss, o);
    if (lid == 0 && isX) g_tt[row] = ss;
}

// ================= kernel 2: fp16 mma.sync GEMM (R12 + refill-after-A-prefetch) =================
__device__ __forceinline__ void issue_stage(uint32_t sb, int kk, int m0, int n0, int tid) {
    uint32_t stb = sb + (uint32_t)(kk & (NSTAGE - 1)) * STG;
    int kbase = kk * BK;
    #pragma unroll
    for (int j = 0; j < 4; j++) {
        int i = tid + j * 256;
        int r = (i >> 2) & 127, c = i & 3;
        uint32_t swc = (uint32_t)(c ^ ((r >> 1) & 3));
        const __half* src;
        uint32_t dst;
        if (i < 512) { // A
            src = g_xh + (long)(m0 + r) * D_ + kbase + c * 8;
            dst = stb + (uint32_t)(r * 64) + swc * 16;
        } else {       // B
            src = g_Xh + (long)(n0 + r) * D_ + kbase + c * 8;
            dst = stb + 8192u + (uint32_t)(r * 64) + swc * 16;
        }
        CP_ASYNC16(dst, src);
    }
    CP_COMMIT();
}

__global__ void __launch_bounds__(256, 2) knn_gemm() {
    extern __shared__ __align__(128) char smem[];
    uint32_t sb = smem_u32(smem);
    int tid = threadIdx.x, wid = tid >> 5, lid = tid & 31;
    int wm = wid >> 1, wn = wid & 1;          // 4x2 warp grid, 32x64 warp tile
    int m0 = blockIdx.x * BM;
    int n0 = blockIdx.y * BN;

    // tt tile
    if (tid < BN) reinterpret_cast<float*>(smem + SM_TT)[tid] = g_tt[n0 + tid];

    float acc[2][8][4];
    #pragma unroll
    for (int mf = 0; mf < 2; mf++)
        #pragma unroll
        for (int nf = 0; nf < 8; nf++)
            #pragma unroll
            for (int k = 0; k < 4; k++) acc[mf][nf][k] = 0.f;

    issue_stage(sb, 0, m0, n0, tid);
    issue_stage(sb, 1, m0, n0, tid);
    issue_stage(sb, 2, m0, n0, tid);

    const int a_r_lane = lid & 15;            // row within 16
    const int a_chi    = lid >> 4;            // chunk low bit
    const int b_n_lane = ((lid >> 4) & 1) * 8 + (lid & 7);
    const int b_chi    = (lid >> 3) & 1;

    for (int kk = 0; kk < KI; ++kk) {
        if (kk < KI - 2)      { CP_WAIT2(); }
        else if (kk == KI - 2){ CP_WAIT1(); }
        else                  { CP_WAIT0(); }
        __syncthreads();

        uint32_t Ab = sb + (uint32_t)(kk & (NSTAGE - 1)) * STG;
        uint32_t Bb = Ab + 8192u;

        // prefetch ALL A fragments for this stage FIRST (critical path),
        // then issue the refill copies behind them.
        uint32_t a_frag[2][2][4];
        #pragma unroll
        for (int ks = 0; ks < 2; ++ks) {
            #pragma unroll
            for (int mf = 0; mf < 2; ++mf) {
                int r = wm * 32 + mf * 16 + a_r_lane;
                uint32_t craw = (uint32_t)(2 * ks + a_chi);
                uint32_t addr = Ab + (uint32_t)(r * 64) + ((craw ^ ((uint32_t)(r >> 1) & 3u)) * 16u);
                LDMX4(a_frag[ks][mf], addr);
            }
        }
        // refill buffer (kk+3)%4 == (kk-1)%4: its previous contents were last
        // read in iter kk-1, and the barrier above proves all warps are past it.
        if (kk + 3 < KI) issue_stage(sb, kk + 3, m0, n0, tid);

        #pragma unroll
        for (int ks = 0; ks < 2; ++ks) {
            uint32_t b4[2][4];
            // prefetch first B fragment of this half
            {
                int n = wn * 64 + 0 * 16 + b_n_lane;
                uint32_t craw = (uint32_t)(2 * ks + b_chi);
                uint32_t addr = Bb + (uint32_t)(n * 64) + ((craw ^ ((uint32_t)(n >> 1) & 3u)) * 16u);
                LDMX4(b4[0], addr);
            }
            #pragma unroll
            for (int np = 0; np < 4; ++np) {
                if (np < 3) {   // prefetch next B fragment before issuing MMAs
                    int n = wn * 64 + (np + 1) * 16 + b_n_lane;
                    uint32_t craw = (uint32_t)(2 * ks + b_chi);
                    uint32_t addr = Bb + (uint32_t)(n * 64) + ((craw ^ ((uint32_t)(n >> 1) & 3u)) * 16u);
                    LDMX4(b4[(np + 1) & 1], addr);
                }
                uint32_t* bc = b4[np & 1];
                MMA16816(acc[0][2 * np],     a_frag[ks][0], bc[0], bc[1]);
                MMA16816(acc[0][2 * np + 1], a_frag[ks][0], bc[2], bc[3]);
                MMA16816(acc[1][2 * np],     a_frag[ks][1], bc[0], bc[1]);
                MMA16816(acc[1][2 * np + 1], a_frag[ks][1], bc[2], bc[3]);
            }
        }
    }

    // ---- epilogue: score = tt - 2*cross; per-row top-2 over this 128-col tile ----
    const float* tts = reinterpret_cast<const float*>(smem + SM_TT);
    unsigned long long* epi = reinterpret_cast<unsigned long long*>(smem + SM_EPI);

    #pragma unroll
    for (int mf = 0; mf < 2; ++mf) {
        #pragma unroll
        for (int h = 0; h < 2; ++h) {
            int R = wm * 32 + mf * 16 + (lid >> 2) + 8 * h;
            unsigned long long b1 = ~0ull, b2 = ~0ull;
            #pragma unroll
            for (int nf = 0; nf < 8; ++nf) {
                #pragma unroll
                for (int j = 0; j < 2; ++j) {
                    int col = wn * 64 + nf * 8 + (lid & 3) * 2 + j;
                    float score = tts[col] - 2.0f * acc[mf][nf][2 * h + j];
                    unsigned long long key = pack_key(score, (unsigned)(n0 + col));
                    if (key < b1) { b2 = b1; b1 = key; }
                    else if (key < b2) { b2 = key; }
                }
            }
            unsigned long long o1 = __shfl_xor_sync(0xffffffffu, b1, 1);
            unsigned long long o2 = __shfl_xor_sync(0xffffffffu, b2, 1);
            merge2(b1, b2, o1, o2);
            o1 = __shfl_xor_sync(0xffffffffu, b1, 2);
            o2 = __shfl_xor_sync(0xffffffffu, b2, 2);
            merge2(b1, b2, o1, o2);
            if ((lid & 3) == 0) {
                epi[R * 4 + wn * 2 + 0] = b1;
                epi[R * 4 + wn * 2 + 1] = b2;
            }
        }
    }
    __syncthreads();
    if (tid < BM) {
        unsigned long long b1 = epi[tid * 4 + 0], b2 = epi[tid * 4 + 1];
        merge2(b1, b2, epi[tid * 4 + 2], epi[tid * 4 + 3]);
        long base = ((long)(m0 + tid) * NT + blockIdx.y) * 2;
        g_part[base] = b1;
        g_part[base + 1] = b2;
    }
}

// ================= kernel 3: shuffle-only global top-4 + exact rescore + gather =================
__global__ void knn_reduce(const float* __restrict__ x, const float* __restrict__ Xt,
                           const float* __restrict__ Yt, float* __restrict__ out) {
    int row = blockIdx.x, tid = threadIdx.x;
    int wid = tid >> 5, lid = tid & 31;
    const unsigned long long* part = g_part + (long)row * NT * 2;

    // per-thread top-2 of its 4 keys
    unsigned long long b1 = ~0ull, b2 = ~0ull;
    #pragma unroll
    for (int j = 0; j < 4; j++) {
        unsigned long long k = part[tid * 4 + j];
        if (k < b1) { b2 = b1; b1 = k; }
        else if (k < b2) { b2 = k; }
    }
    // warp shuffle-merge -> warp top-2
    #pragma unroll
    for (int o = 16; o; o >>= 1) {
        unsigned long long o1 = __shfl_xor_sync(0xffffffffu, b1, o);
        unsigned long long o2 = __shfl_xor_sync(0xffffffffu, b2, o);
        merge2(b1, b2, o1, o2);
    }
    __shared__ unsigned long long w2[16];
    if (lid == 0) { w2[wid * 2] = b1; w2[wid * 2 + 1] = b2; }
    __syncthreads();

    // warp 0: extract global top-4 of the 16 candidates (keys distinct by idx)
    __shared__ unsigned cand[4];
    if (wid == 0) {
        unsigned long long k = (lid < 16) ? w2[lid] : ~0ull;
        #pragma unroll
        for (int r = 0; r < 4; r++) {
            unsigned long long m = k;
            #pragma unroll
            for (int o = 16; o; o >>= 1) {
                unsigned long long om = __shfl_xor_sync(0xffffffffu, m, o);
                if (om < m) m = om;
            }
            if (lid == 0) cand[r] = (unsigned)(m & 0xffffffffu);
            if (k == m) k = ~0ull;   // remove winner (unique)
        }
    }
    __syncthreads();

    // exact fp32 rescore of 4 candidates (one per warp, warps 0-3)
    __shared__ float sscore[4];
    __shared__ unsigned sidx[4];
    if (wid < 4) {
        unsigned idx = cand[wid];
        const float* xr = x + (long)row * D_;
        const float* tr = Xt + (long)idx * D_;
        float p = 0.f;
        #pragma unroll
        for (int e = lid; e < D_; e += 32) p += xr[e] * tr[e];
        #pragma unroll
        for (int o = 16; o; o >>= 1) p += __shfl_xor_sync(0xffffffffu, p, o);
        if (lid == 0) { sscore[wid] = g_tt[idx] - 2.0f * p; sidx[wid] = idx; }
    }
    __syncthreads();
    __shared__ unsigned winner;
    if (tid == 0) {
        float bs = sscore[0]; unsigned bi = sidx[0];
        #pragma unroll
        for (int i = 1; i < 4; i++)
            if (sscore[i] < bs || (sscore[i] == bs && sidx[i] < bi)) { bs = sscore[i]; bi = sidx[i]; }
        winner = bi;
    }
    __syncthreads();
    if (tid < 24) out[row * 24 + tid] = Yt[(long)winner * 24 + tid];
}

// ================= launch =================
extern "C" void kernel_launch(void* const* d_in, const int* in_sizes, int n_in,
                              void* d_out, int out_size) {
    const float* x  = (const float*)d_in[0];   // [2048, 24, 16]
    const float* Xt = (const float*)d_in[1];   // [65536, 384]
    const float* Yt = (const float*)d_in[2];   // [65536, 24, 1]
    float* out = (float*)d_out;                // [2048, 24, 1]

    cudaFuncSetAttribute(knn_gemm, cudaFuncAttributeMaxDynamicSharedMemorySize, SMEM_TOTAL);

    int total_warps = N_TOTAL + M_TOTAL;               // 67584
    knn_prep<<<total_warps / 8, 256>>>(Xt, x);
    knn_gemm<<<dim3(MT, NT), 256, SMEM_TOTAL>>>();
    knn_reduce<<<M_TOTAL, 256>>>(x, Xt, Yt, out);
}

// round 16
// speedup vs baseline: 1.2908x; 1.0079x over previous
#include <cuda_runtime.h>
#include <cuda_fp16.h>
#include <cstdint>

// ---------------- problem constants ----------------
static constexpr int M_TOTAL = 2048;     // queries
static constexpr int N_TOTAL = 65536;    // train points
static constexpr int D_      = 384;      // feature dim
static constexpr int BM = 128;           // CTA M tile
static constexpr int BN = 128;           // CTA N tile
static constexpr int BK = 32;            // K per smem stage
static constexpr int KI = D_ / BK;       // 12
static constexpr int MT = M_TOTAL / BM;  // 16
static constexpr int NT = N_TOTAL / BN;  // 512
static constexpr int NSTAGE = 4;

// smem: 4 stages x (A 8KB | B 8KB) + tt(512B) + epi(4KB)
static constexpr int STG     = 16384;
static constexpr int SM_TT   = NSTAGE * STG;     // 65536
static constexpr int SM_EPI  = SM_TT + 512;      // 66048
static constexpr int SMEM_TOTAL = SM_EPI + 128 * 4 * 8; // 70144

// ---------------- device scratch (no allocs allowed) ----------------
__device__ __half g_Xh[(long)N_TOTAL * D_];
__device__ __half g_xh[(long)M_TOTAL * D_];
__device__ float  g_tt[N_TOTAL];
__device__ unsigned long long g_part[(long)M_TOTAL * NT * 2];

// ---------------- helpers ----------------
__device__ __forceinline__ uint32_t smem_u32(const void* p) {
    uint32_t a;
    asm("{ .reg .u64 t; cvta.to.shared.u64 t, %1; cvt.u32.u64 %0, t; }" : "=r"(a) : "l"(p));
    return a;
}
__device__ __forceinline__ unsigned long long pack_key(float s, unsigned idx) {
    unsigned u = __float_as_uint(s);
    u = (u & 0x80000000u) ? ~u : (u | 0x80000000u);
    return ((unsigned long long)u << 32) | idx;
}
#define CP_ASYNC16(dst, src) \
    asm volatile("cp.async.cg.shared.global [%0], [%1], 16;" :: "r"(dst), "l"(src) : "memory")
#define CP_COMMIT()  asm volatile("cp.async.commit_group;" ::: "memory")
#define CP_WAIT2()   asm volatile("cp.async.wait_group 2;" ::: "memory")
#define CP_WAIT1()   asm volatile("cp.async.wait_group 1;" ::: "memory")
#define CP_WAIT0()   asm volatile("cp.async.wait_group 0;" ::: "memory")

#define LDMX4(r, addr) \
    asm volatile("ldmatrix.sync.aligned.m8n8.x4.shared.b16 {%0,%1,%2,%3}, [%4];" \
        : "=r"((r)[0]), "=r"((r)[1]), "=r"((r)[2]), "=r"((r)[3]) : "r"(addr))

#define MMA16816(d, a, b0, b1) \
    asm volatile("mma.sync.aligned.m16n8k16.row.col.f32.f16.f16.f32 " \
        "{%0,%1,%2,%3}, {%4,%5,%6,%7}, {%8,%9}, {%0,%1,%2,%3};" \
        : "+f"((d)[0]), "+f"((d)[1]), "+f"((d)[2]), "+f"((d)[3]) \
        : "r"((a)[0]), "r"((a)[1]), "r"((a)[2]), "r"((a)[3]), "r"(b0), "r"(b1))

// merge two ascending pairs (b1<=b2), (o1<=o2) -> global top-2 in (b1,b2)
__device__ __forceinline__ void merge2(unsigned long long& b1, unsigned long long& b2,
                                       unsigned long long o1, unsigned long long o2) {
    if (o1 < b1) { b2 = (b1 < o2) ? b1 : o2; b1 = o1; }
    else         { b2 = (b2 < o1) ? b2 : o1; }
}

// ================= kernel 1: fp16 convert + tt =================
__global__ void knn_prep(const float* __restrict__ Xt, const float* __restrict__ x) {
    int gw  = (blockIdx.x * blockDim.x + threadIdx.x) >> 5;
    int lid = threadIdx.x & 31;
    if (gw >= N_TOTAL + M_TOTAL) return;
    bool isX = gw < N_TOTAL;
    long row = isX ? gw : (gw - N_TOTAL);
    const float* src = (isX ? Xt : x) + row * D_;
    __half* dst = (isX ? g_Xh : g_xh) + row * D_;

    float ss = 0.f;
    #pragma unroll
    for (int i = lid; i < D_ / 4; i += 32) {
        float4 v = reinterpret_cast<const float4*>(src)[i];
        ss += v.x * v.x + v.y * v.y + v.z * v.z + v.w * v.w;
        __half2* hp = reinterpret_cast<__half2*>(dst + i * 4);
        hp[0] = __floats2half2_rn(v.x, v.y);
        hp[1] = __floats2half2_rn(v.z, v.w);
    }
    #pragma unroll
    for (int o = 16; o; o >>= 1) ss += __shfl_xor_sync(0xffffffffu, ss, o);
    if (lid == 0 && isX) g_tt[row] = ss;
}

// ================= kernel 2: fp16 mma.sync GEMM (R15 + peeled first-B before refill) =================
__device__ __forceinline__ void issue_stage(uint32_t sb, int kk, int m0, int n0, int tid) {
    uint32_t stb = sb + (uint32_t)(kk & (NSTAGE - 1)) * STG;
    int kbase = kk * BK;
    #pragma unroll
    for (int j = 0; j < 4; j++) {
        int i = tid + j * 256;
        int r = (i >> 2) & 127, c = i & 3;
        uint32_t swc = (uint32_t)(c ^ ((r >> 1) & 3));
        const __half* src;
        uint32_t dst;
        if (i < 512) { // A
            src = g_xh + (long)(m0 + r) * D_ + kbase + c * 8;
            dst = stb + (uint32_t)(r * 64) + swc * 16;
        } else {       // B
            src = g_Xh + (long)(n0 + r) * D_ + kbase + c * 8;
            dst = stb + 8192u + (uint32_t)(r * 64) + swc * 16;
        }
        CP_ASYNC16(dst, src);
    }
    CP_COMMIT();
}

__global__ void __launch_bounds__(256, 2) knn_gemm() {
    extern __shared__ __align__(128) char smem[];
    uint32_t sb = smem_u32(smem);
    int tid = threadIdx.x, wid = tid >> 5, lid = tid & 31;
    int wm = wid >> 1, wn = wid & 1;          // 4x2 warp grid, 32x64 warp tile
    int m0 = blockIdx.x * BM;
    int n0 = blockIdx.y * BN;

    // tt tile
    if (tid < BN) reinterpret_cast<float*>(smem + SM_TT)[tid] = g_tt[n0 + tid];

    float acc[2][8][4];
    #pragma unroll
    for (int mf = 0; mf < 2; mf++)
        #pragma unroll
        for (int nf = 0; nf < 8; nf++)
            #pragma unroll
            for (int k = 0; k < 4; k++) acc[mf][nf][k] = 0.f;

    issue_stage(sb, 0, m0, n0, tid);
    issue_stage(sb, 1, m0, n0, tid);
    issue_stage(sb, 2, m0, n0, tid);

    const int a_r_lane = lid & 15;            // row within 16
    const int a_chi    = lid >> 4;            // chunk low bit
    const int b_n_lane = ((lid >> 4) & 1) * 8 + (lid & 7);
    const int b_chi    = (lid >> 3) & 1;

    for (int kk = 0; kk < KI; ++kk) {
        if (kk < KI - 2)      { CP_WAIT2(); }
        else if (kk == KI - 2){ CP_WAIT1(); }
        else                  { CP_WAIT0(); }
        __syncthreads();

        uint32_t Ab = sb + (uint32_t)(kk & (NSTAGE - 1)) * STG;
        uint32_t Bb = Ab + 8192u;

        // 1) prefetch ALL A fragments for this stage (critical path)
        uint32_t a_frag[2][2][4];
        #pragma unroll
        for (int ks = 0; ks < 2; ++ks) {
            #pragma unroll
            for (int mf = 0; mf < 2; ++mf) {
                int r = wm * 32 + mf * 16 + a_r_lane;
                uint32_t craw = (uint32_t)(2 * ks + a_chi);
                uint32_t addr = Ab + (uint32_t)(r * 64) + ((craw ^ ((uint32_t)(r >> 1) & 3u)) * 16u);
                LDMX4(a_frag[ks][mf], addr);
            }
        }
        // 2) peel: first B fragment of ks=0 (also feeds the first MMA)
        uint32_t b4[2][4];
        {
            int n = wn * 64 + b_n_lane;
            uint32_t craw = (uint32_t)(0 + b_chi);
            uint32_t addr = Bb + (uint32_t)(n * 64) + ((craw ^ ((uint32_t)(n >> 1) & 3u)) * 16u);
            LDMX4(b4[0], addr);
        }
        // 3) refill behind all first-MMA-feeding loads.
        // Buffer (kk+3)%4 == (kk-1)%4: last read in iter kk-1, proven done by the barrier.
        if (kk + 3 < KI) issue_stage(sb, kk + 3, m0, n0, tid);

        // 4) MMA stream
        #pragma unroll
        for (int ks = 0; ks < 2; ++ks) {
            if (ks == 1) {   // first B fragment of second half
                int n = wn * 64 + b_n_lane;
                uint32_t craw = (uint32_t)(2 + b_chi);
                uint32_t addr = Bb + (uint32_t)(n * 64) + ((craw ^ ((uint32_t)(n >> 1) & 3u)) * 16u);
                LDMX4(b4[0], addr);
            }
            #pragma unroll
            for (int np = 0; np < 4; ++np) {
                if (np < 3) {   // prefetch next B fragment before issuing MMAs
                    int n = wn * 64 + (np + 1) * 16 + b_n_lane;
                    uint32_t craw = (uint32_t)(2 * ks + b_chi);
                    uint32_t addr = Bb + (uint32_t)(n * 64) + ((craw ^ ((uint32_t)(n >> 1) & 3u)) * 16u);
                    LDMX4(b4[(np + 1) & 1], addr);
                }
                uint32_t* bc = b4[np & 1];
                MMA16816(acc[0][2 * np],     a_frag[ks][0], bc[0], bc[1]);
                MMA16816(acc[0][2 * np + 1], a_frag[ks][0], bc[2], bc[3]);
                MMA16816(acc[1][2 * np],     a_frag[ks][1], bc[0], bc[1]);
                MMA16816(acc[1][2 * np + 1], a_frag[ks][1], bc[2], bc[3]);
            }
        }
    }

    // ---- epilogue: score = tt - 2*cross; per-row top-2 over this 128-col tile ----
    const float* tts = reinterpret_cast<const float*>(smem + SM_TT);
    unsigned long long* epi = reinterpret_cast<unsigned long long*>(smem + SM_EPI);

    #pragma unroll
    for (int mf = 0; mf < 2; ++mf) {
        #pragma unroll
        for (int h = 0; h < 2; ++h) {
            int R = wm * 32 + mf * 16 + (lid >> 2) + 8 * h;
            unsigned long long b1 = ~0ull, b2 = ~0ull;
            #pragma unroll
            for (int nf = 0; nf < 8; ++nf) {
                #pragma unroll
                for (int j = 0; j < 2; ++j) {
                    int col = wn * 64 + nf * 8 + (lid & 3) * 2 + j;
                    float score = tts[col] - 2.0f * acc[mf][nf][2 * h + j];
                    unsigned long long key = pack_key(score, (unsigned)(n0 + col));
                    if (key < b1) { b2 = b1; b1 = key; }
                    else if (key < b2) { b2 = key; }
                }
            }
            unsigned long long o1 = __shfl_xor_sync(0xffffffffu, b1, 1);
            unsigned long long o2 = __shfl_xor_sync(0xffffffffu, b2, 1);
            merge2(b1, b2, o1, o2);
            o1 = __shfl_xor_sync(0xffffffffu, b1, 2);
            o2 = __shfl_xor_sync(0xffffffffu, b2, 2);
            merge2(b1, b2, o1, o2);
            if ((lid & 3) == 0) {
                epi[R * 4 + wn * 2 + 0] = b1;
                epi[R * 4 + wn * 2 + 1] = b2;
            }
        }
    }
    __syncthreads();
    if (tid < BM) {
        unsigned long long b1 = epi[tid * 4 + 0], b2 = epi[tid * 4 + 1];
        merge2(b1, b2, epi[tid * 4 + 2], epi[tid * 4 + 3]);
        long base = ((long)(m0 + tid) * NT + blockIdx.y) * 2;
        g_part[base] = b1;
        g_part[base + 1] = b2;
    }
}

// ================= kernel 3: shuffle-only global top-4 + exact rescore + gather =================
__global__ void knn_reduce(const float* __restrict__ x, const float* __restrict__ Xt,
                           const float* __restrict__ Yt, float* __restrict__ out) {
    int row = blockIdx.x, tid = threadIdx.x;
    int wid = tid >> 5, lid = tid & 31;
    const unsigned long long* part = g_part + (long)row * NT * 2;

    // per-thread top-2 of its 4 keys
    unsigned long long b1 = ~0ull, b2 = ~0ull;
    #pragma unroll
    for (int j = 0; j < 4; j++) {
        unsigned long long k = part[tid * 4 + j];
        if (k < b1) { b2 = b1; b1 = k; }
        else if (k < b2) { b2 = k; }
    }
    // warp shuffle-merge -> warp top-2
    #pragma unroll
    for (int o = 16; o; o >>= 1) {
        unsigned long long o1 = __shfl_xor_sync(0xffffffffu, b1, o);
        unsigned long long o2 = __shfl_xor_sync(0xffffffffu, b2, o);
        merge2(b1, b2, o1, o2);
    }
    __shared__ unsigned long long w2[16];
    if (lid == 0) { w2[wid * 2] = b1; w2[wid * 2 + 1] = b2; }
    __syncthreads();

    // warp 0: extract global top-4 of the 16 candidates (keys distinct by idx)
    __shared__ unsigned cand[4];
    if (wid == 0) {
        unsigned long long k = (lid < 16) ? w2[lid] : ~0ull;
        #pragma unroll
        for (int r = 0; r < 4; r++) {
            unsigned long long m = k;
            #pragma unroll
            for (int o = 16; o; o >>= 1) {
                unsigned long long om = __shfl_xor_sync(0xffffffffu, m, o);
                if (om < m) m = om;
            }
            if (lid == 0) cand[r] = (unsigned)(m & 0xffffffffu);
            if (k == m) k = ~0ull;   // remove winner (unique)
        }
    }
    __syncthreads();

    // exact fp32 rescore of 4 candidates (one per warp, warps 0-3)
    __shared__ float sscore[4];
    __shared__ unsigned sidx[4];
    if (wid < 4) {
        unsigned idx = cand[wid];
        const float* xr = x + (long)row * D_;
        const float* tr = Xt + (long)idx * D_;
        float p = 0.f;
        #pragma unroll
        for (int e = lid; e < D_; e += 32) p += xr[e] * tr[e];
        #pragma unroll
        for (int o = 16; o; o >>= 1) p += __shfl_xor_sync(0xffffffffu, p, o);
        if (lid == 0) { sscore[wid] = g_tt[idx] - 2.0f * p; sidx[wid] = idx; }
    }
    __syncthreads();
    __shared__ unsigned winner;
    if (tid == 0) {
        float bs = sscore[0]; unsigned bi = sidx[0];
        #pragma unroll
        for (int i = 1; i < 4; i++)
            if (sscore[i] < bs || (sscore[i] == bs && sidx[i] < bi)) { bs = sscore[i]; bi = sidx[i]; }
        winner = bi;
    }
    __syncthreads();
    if (tid < 24) out[row * 24 + tid] = Yt[(long)winner * 24 + tid];
}

// ================= launch =================
extern "C" void kernel_launch(void* const* d_in, const int* in_sizes, int n_in,
                              void* d_out, int out_size) {
    const float* x  = (const float*)d_in[0];   // [2048, 24, 16]
    const float* Xt = (const float*)d_in[1];   // [65536, 384]
    const float* Yt = (const float*)d_in[2];   // [65536, 24, 1]
    float* out = (float*)d_out;                // [2048, 24, 1]

    cudaFuncSetAttribute(knn_gemm, cudaFuncAttributeMaxDynamicSharedMemorySize, SMEM_TOTAL);

    int total_warps = N_TOTAL + M_TOTAL;               // 67584
    knn_prep<<<total_warps / 8, 256>>>(Xt, x);
    knn_gemm<<<dim3(MT, NT), 256, SMEM_TOTAL>>>();
    knn_reduce<<<M_TOTAL, 256>>>(x, Xt, Yt, out);
}